// round 13
// baseline (speedup 1.0000x reference)
#include <cuda_runtime.h>

#define FULLMASK 0xffffffffu
#define WPB 8   // warps (rays) per block

__device__ __forceinline__ float warpExclProd(float p, int lane) {
    float incl = p;
    #pragma unroll
    for (int d = 1; d < 32; d <<= 1) {
        float o = __shfl_up_sync(FULLMASK, incl, d);
        if (lane >= d) incl *= o;
    }
    float excl = __shfl_up_sync(FULLMASK, incl, 1);
    if (lane == 0) excl = 1.0f;
    return excl;
}

__device__ __forceinline__ float warpInclSum(float v, int lane) {
    #pragma unroll
    for (int d = 1; d < 32; d <<= 1) {
        float o = __shfl_up_sync(FULLMASK, v, d);
        if (lane >= d) v += o;
    }
    return v;
}

// 1-stage partial reduction: lane l holds v_l + v_{l^16}. Lanes 0..15 stage 16
// partials; the final add happens in the (otherwise idle) output phase.
__device__ __forceinline__ float warpSum1(float v) {
    return v + __shfl_xor_sync(FULLMASK, v, 16);
}

// #{l in [0,32) : E_l <= u} for a sorted lane-distributed float array.
// 5 bisection probes + 1 final probe (33 outcomes need 6 comparisons).
__device__ __forceinline__ int cntLE_f(float E, float u) {
    int lo = 0;
    #pragma unroll
    for (int s = 16; s; s >>= 1) {
        float v = __shfl_sync(FULLMASK, E, lo + s - 1);
        if (v <= u) lo += s;
    }
    float v = __shfl_sync(FULLMASK, E, lo);
    if (v <= u) lo += 1;
    return lo;
}

__global__ void __launch_bounds__(WPB * 32, 8)
nerf_kernel(const float* __restrict__ rays,
            const float* __restrict__ sigc,
            const float* __restrict__ rgbc,
            const float* __restrict__ sigf,
            const float* __restrict__ rgbf,
            float* __restrict__ out,
            int N)
{
    __shared__ __align__(16) float smem[WPB][128];   // merged z
    __shared__ __align__(16) float osm[WPB][164];    // 10 q's x 16 partials + fr
    const int lane = threadIdx.x & 31;
    const int w    = threadIdx.x >> 5;
    const int ray  = blockIdx.x * WPB + w;

    if (ray < N) {
        float* ZM = smem[w];          // 128 merged z

        float2 nf = *(const float2*)(rays + (size_t)ray * 8 + 6);
        const float nr = nf.x, fr = nf.y;
        const float dzs = (fr - nr) * 0.015625f;     // (far-near)/64
        const float invstep = 1.0f / dzs;

        // ============== coarse pass: lane handles samples 2l, 2l+1 ==============
        const int s0 = lane * 2, s1 = s0 + 1;
        float z0 = nr + (float)s0 * dzs;
        float z1 = nr + (float)s1 * dzs;
        float d0 = z1 - z0;
        float d1 = (lane == 31) ? 1e10f : ((nr + (float)(s1 + 1) * dzs) - z1);

        float2 sg = *(const float2*)(sigc + (size_t)ray * 64 + s0);
        float e0 = __expf(-d0 * fmaxf(sg.x, 0.0f));
        float e1 = __expf(-d1 * fmaxf(sg.y, 0.0f));
        float a0 = 1.0f - e0, a1 = 1.0f - e1;
        float f0 = e0 + 1e-10f, f1 = e1 + 1e-10f;

        float E  = warpExclProd(f0 * f1, lane);
        float T0 = E, T1 = E * f0;
        float w0 = a0 * T0, w1 = a1 * T1;

        const float* rp = rgbc + (size_t)ray * 192 + lane * 6;
        float2 ra  = *(const float2*)(rp);
        float2 rb  = *(const float2*)(rp + 2);
        float2 rc2 = *(const float2*)(rp + 4);

        float pR = warpSum1(w0 * ra.x + w1 * rb.y);
        float pG = warpSum1(w0 * ra.y + w1 * rc2.x);
        float pB = warpSum1(w0 * rb.x + w1 * rc2.y);
        float pW = warpSum1(w0 + w1);
        float pD = warpSum1(w0 * z0 + w1 * z1);
        if (lane < 16) {
            osm[w][0   + lane] = pR;   // q0 accR
            osm[w][16  + lane] = pG;   // q1 accG
            osm[w][32  + lane] = pB;   // q2 accB
            osm[w][48  + lane] = pW;   // q3 wsum
            osm[w][64  + lane] = pD;   // q4 dep
        }
        if (lane == 0) osm[w][160] = fr;

        // ---- cdf over weights[1..62] + 1e-5: registers, 2 entries/lane ----
        float t0c = (s0 >= 1)  ? (w0 + 1e-5f) : 0.0f;
        float t1c = (s1 <= 62) ? (w1 + 1e-5f) : 0.0f;
        float incl = warpInclSum(t0c + t1c, lane);
        float totw = __shfl_sync(FULLMASK, incl, 31);
        float exS  = __shfl_up_sync(FULLMASK, incl, 1);
        if (lane == 0) exS = 0.0f;
        float inv = 1.0f / totw;
        float cdfE = (exS + t0c) * inv;
        float cdfO = (lane == 31) ? 3.0e38f : (incl * inv);

        // ============== fine z: inverse CDF via shuffle search, j = 2l, 2l+1 =========
        float zfine[2];
        int   cfin[2];   // c_j ≈ #{z_coarse <= z_fine_j} (analytic; monotonized below)
        #pragma unroll
        for (int q = 0; q < 2; q++) {
            int j = 2 * lane + q;
            float u = (j == 63) ? 1.0f : (float)j * (1.0f / 63.0f);

            // ind = searchsorted(cdf[0..62], u, 'right')
            int ne = cntLE_f(cdfE, u);                       // in [1,32]
            float oprev = __shfl_sync(FULLMASK, cdfO, ne - 1);
            int t = (oprev <= u) ? 1 : 0;
            int ind = 2 * ne - 1 + t;                        // in [1,63]
            float eprev = __shfl_sync(FULLMASK, cdfE, ne - 1);
            float enext = __shfl_sync(FULLMASK, cdfE, min(ne, 31));

            int below = ind - 1;
            int above = ind < 62 ? ind : 62;
            float cb = t ? oprev : eprev;
            float ca = (t || ind == 63) ? enext : oprev;

            float bb = nr + ((float)below + 0.5f) * dzs;     // bin midpoints
            float ba = nr + ((float)above + 0.5f) * dzs;
            float den = ca - cb;
            if (den < 1e-5f) den = 1.0f;
            float zf = bb + __fdividef(u - cb, den) * (ba - bb);
            zfine[q] = zf;

            // analytic coarse-count; ties resolved by the monotonize pass
            int c = (int)((zf - nr) * invstep) + 1;
            cfin[q] = max(0, min(64, c));
        }

        // ============== monotonize c (running max) — makes the merge a bijection ====
        int c0 = cfin[0], c1 = cfin[1];
        {
            int hi = max(c0, c1);
            int scan = hi;
            #pragma unroll
            for (int d = 1; d < 32; d <<= 1) {
                int o = __shfl_up_sync(FULLMASK, scan, d);
                if (lane >= d) scan = max(scan, o);
            }
            int ex = __shfl_up_sync(FULLMASK, scan, 1);
            if (lane == 0) ex = 0;
            c0 = max(ex, c0);
            c1 = max(c0, c1);
        }
        ZM[2 * lane + c0]     = zfine[0];      // fine merged position = j + c'_j
        ZM[2 * lane + 1 + c1] = zfine[1];

        // ============== coarse placement via interval fill ==============
        // cnt(i) = #{j : c'_j <= i} is constant (= j+1) on [c'_j, c'_{j+1}).
        // Lane l owns j0=2l (gap [c0,c1), offset 2l+1) and j1=2l+1 (gap
        // [c1,cnext), offset 2l+2); lane 0 also fills [0,c0) at offset 0.
        // Intervals partition [0,64) -> every ZM slot written exactly once.
        {
            int cnext = __shfl_down_sync(FULLMASK, c0, 1);
            if (lane == 31) cnext = 64;
            if (lane == 0) {
                for (int i = 0; i < c0; ++i)
                    ZM[i] = nr + (float)i * dzs;
            }
            int base = 2 * lane + 1;
            for (int i = c0; i < cnext; ++i)
                ZM[i + base + (i >= c1 ? 1 : 0)] = nr + (float)i * dzs;
        }
        __syncwarp();

        // ============== fine composite: lane handles samples 4l..4l+3 ==============
        float4 zq = *(const float4*)&ZM[4 * lane];
        float zn  = (lane == 31) ? 0.0f : ZM[4 * lane + 4];
        float dd0 = zq.y - zq.x;
        float dd1 = zq.z - zq.y;
        float dd2 = zq.w - zq.z;
        float dd3 = (lane == 31) ? 1e10f : (zn - zq.w);

        float4 sg4 = *(const float4*)(sigf + (size_t)ray * 128 + 4 * lane);
        float ee0 = __expf(-dd0 * fmaxf(sg4.x, 0.0f));
        float ee1 = __expf(-dd1 * fmaxf(sg4.y, 0.0f));
        float ee2 = __expf(-dd2 * fmaxf(sg4.z, 0.0f));
        float ee3 = __expf(-dd3 * fmaxf(sg4.w, 0.0f));
        float fa0 = 1.0f - ee0, fa1 = 1.0f - ee1, fa2 = 1.0f - ee2, fa3 = 1.0f - ee3;
        float ff0 = ee0 + 1e-10f, ff1 = ee1 + 1e-10f, ff2 = ee2 + 1e-10f, ff3 = ee3 + 1e-10f;

        float E2 = warpExclProd(ff0 * ff1 * ff2 * ff3, lane);
        float U0 = E2, U1 = U0 * ff0, U2 = U1 * ff1, U3 = U2 * ff2;
        float v0 = fa0 * U0, v1 = fa1 * U1, v2 = fa2 * U2, v3 = fa3 * U3;

        const float* rfp = rgbf + (size_t)ray * 384 + 12 * lane;
        float4 q0 = *(const float4*)(rfp);
        float4 q1 = *(const float4*)(rfp + 4);
        float4 q2 = *(const float4*)(rfp + 8);

        float pFR = warpSum1(v0 * q0.x + v1 * q0.w + v2 * q1.z + v3 * q2.y);
        float pFG = warpSum1(v0 * q0.y + v1 * q1.x + v2 * q1.w + v3 * q2.z);
        float pFB = warpSum1(v0 * q0.z + v1 * q1.y + v2 * q2.x + v3 * q2.w);
        float pFW = warpSum1(v0 + v1 + v2 + v3);
        float pFD = warpSum1(v0 * zq.x + v1 * zq.y + v2 * zq.z + v3 * zq.w);
        if (lane < 16) {
            osm[w][80  + lane] = pFR;  // q5 fR
            osm[w][96  + lane] = pFG;  // q6 fG
            osm[w][112 + lane] = pFB;  // q7 fB
            osm[w][128 + lane] = pFW;  // q8 wsF
            osm[w][144 + lane] = pFD;  // q9 depF
        }
    }
    __syncthreads();

    // ============== output phase: finish reductions + coalesced writes ==============
    const int t = threadIdx.x;
    const size_t R0 = (size_t)blockIdx.x * WPB;
    const int nblk = min(WPB, N - (int)R0);
    const size_t NN = (size_t)N;

    #define SUMQ(r, q) ({ const float4* _b = (const float4*)&osm[(r)][16 * (q)]; \
                          float4 _p0 = _b[0], _p1 = _b[1], _p2 = _b[2], _p3 = _b[3]; \
                          (((_p0.x + _p0.y) + (_p0.z + _p0.w)) +                 \
                           ((_p1.x + _p1.y) + (_p1.z + _p1.w))) +                \
                          (((_p2.x + _p2.y) + (_p2.z + _p2.w)) +                 \
                           ((_p3.x + _p3.y) + (_p3.z + _p3.w))); })

    if (t < 24) {                               // coarse rgb
        int r = t / 3, c = t % 3;
        if (r < nblk) out[3 * R0 + t] = SUMQ(r, c) + 1.0f - SUMQ(r, 3);
    } else if (t < 32) {                        // coarse alpha (weights_sum)
        int r = t - 24;
        if (r < nblk) out[3 * NN + R0 + r] = SUMQ(r, 3);
    } else if (t < 40) {                        // coarse depth
        int r = t - 32;
        if (r < nblk) out[4 * NN + R0 + r] = SUMQ(r, 4) + (1.0f - SUMQ(r, 3)) * osm[r][160];
    } else if (t < 64) {                        // fine rgb
        int j = t - 40;
        int r = j / 3, c = j % 3;
        if (r < nblk) out[5 * NN + 3 * R0 + j] = SUMQ(r, 5 + c) + 1.0f - SUMQ(r, 8);
    } else if (t < 72) {                        // fine alpha
        int r = t - 64;
        if (r < nblk) out[8 * NN + R0 + r] = SUMQ(r, 8);
    } else if (t < 80) {                        // fine depth
        int r = t - 72;
        if (r < nblk) out[9 * NN + R0 + r] = SUMQ(r, 9) + (1.0f - SUMQ(r, 8)) * osm[r][160];
    }
    #undef SUMQ
}

extern "C" void kernel_launch(void* const* d_in, const int* in_sizes, int n_in,
                              void* d_out, int out_size) {
    const float* rays = (const float*)d_in[0];
    const float* sc   = (const float*)d_in[1];
    const float* rc   = (const float*)d_in[2];
    const float* sf   = (const float*)d_in[3];
    const float* rf   = (const float*)d_in[4];
    float* out = (float*)d_out;
    int N = in_sizes[0] / 8;
    int blocks = (N + WPB - 1) / WPB;
    nerf_kernel<<<blocks, WPB * 32>>>(rays, sc, rc, sf, rf, out, N);
}

// round 14
// speedup vs baseline: 1.0374x; 1.0374x over previous
#include <cuda_runtime.h>

#define FULLMASK 0xffffffffu
#define WPB 8   // warps (rays) per block

__device__ __forceinline__ float warpExclProd(float p, int lane) {
    float incl = p;
    #pragma unroll
    for (int d = 1; d < 32; d <<= 1) {
        float o = __shfl_up_sync(FULLMASK, incl, d);
        if (lane >= d) incl *= o;
    }
    float excl = __shfl_up_sync(FULLMASK, incl, 1);
    if (lane == 0) excl = 1.0f;
    return excl;
}

__device__ __forceinline__ float warpInclSum(float v, int lane) {
    #pragma unroll
    for (int d = 1; d < 32; d <<= 1) {
        float o = __shfl_up_sync(FULLMASK, v, d);
        if (lane >= d) v += o;
    }
    return v;
}

// 1-stage partial reduction: lane l holds v_l + v_{l^16}. Lanes 0..15 stage 16
// partials; the final add happens in the (otherwise idle) output phase.
__device__ __forceinline__ float warpSum1(float v) {
    return v + __shfl_xor_sync(FULLMASK, v, 16);
}

// #{l in [0,32) : E_l <= u} for a sorted lane-distributed float array.
// 5 bisection probes + 1 final probe (33 outcomes need 6 comparisons).
__device__ __forceinline__ int cntLE_f(float E, float u) {
    int lo = 0;
    #pragma unroll
    for (int s = 16; s; s >>= 1) {
        float v = __shfl_sync(FULLMASK, E, lo + s - 1);
        if (v <= u) lo += s;
    }
    float v = __shfl_sync(FULLMASK, E, lo);
    if (v <= u) lo += 1;
    return lo;
}

// same for a sorted lane-distributed int array
__device__ __forceinline__ int cntLE_i(int E, int u) {
    int lo = 0;
    #pragma unroll
    for (int s = 16; s; s >>= 1) {
        int v = __shfl_sync(FULLMASK, E, lo + s - 1);
        if (v <= u) lo += s;
    }
    int v = __shfl_sync(FULLMASK, E, lo);
    if (v <= u) lo += 1;
    return lo;
}

__global__ void __launch_bounds__(WPB * 32, 6)
nerf_kernel(const float* __restrict__ rays,
            const float* __restrict__ sigc,
            const float* __restrict__ rgbc,
            const float* __restrict__ sigf,
            const float* __restrict__ rgbf,
            float* __restrict__ out,
            int N)
{
    __shared__ __align__(16) float smem[WPB][128];   // merged z
    __shared__ __align__(16) float osm[WPB][164];    // 10 q's x 16 partials + fr
    const int lane = threadIdx.x & 31;
    const int w    = threadIdx.x >> 5;
    const int ray  = blockIdx.x * WPB + w;

    if (ray < N) {
        float* ZM = smem[w];          // 128 merged z

        float2 nf = *(const float2*)(rays + (size_t)ray * 8 + 6);
        const float nr = nf.x, fr = nf.y;
        const float dzs = (fr - nr) * 0.015625f;     // (far-near)/64
        const float invstep = 1.0f / dzs;

        // ---- EARLY ISSUE of fine-pass loads: consumed after the merge; keeping
        // them resident (regs ~42, occ 6 CTA/SM) overlaps their DRAM latency
        // with the whole CDF/search/merge section. ----
        float4 sg4 = *(const float4*)(sigf + (size_t)ray * 128 + 4 * lane);
        const float* rfp = rgbf + (size_t)ray * 384 + 12 * lane;
        float4 q0 = *(const float4*)(rfp);
        float4 q1 = *(const float4*)(rfp + 4);
        float4 q2 = *(const float4*)(rfp + 8);

        // ============== coarse pass: lane handles samples 2l, 2l+1 ==============
        const int s0 = lane * 2, s1 = s0 + 1;
        float z0 = nr + (float)s0 * dzs;
        float z1 = nr + (float)s1 * dzs;
        float d0 = z1 - z0;
        float d1 = (lane == 31) ? 1e10f : ((nr + (float)(s1 + 1) * dzs) - z1);

        float2 sg = *(const float2*)(sigc + (size_t)ray * 64 + s0);
        float e0 = __expf(-d0 * fmaxf(sg.x, 0.0f));
        float e1 = __expf(-d1 * fmaxf(sg.y, 0.0f));
        float a0 = 1.0f - e0, a1 = 1.0f - e1;
        float f0 = e0 + 1e-10f, f1 = e1 + 1e-10f;

        float E  = warpExclProd(f0 * f1, lane);
        float T0 = E, T1 = E * f0;
        float w0 = a0 * T0, w1 = a1 * T1;

        const float* rp = rgbc + (size_t)ray * 192 + lane * 6;
        float2 ra  = *(const float2*)(rp);
        float2 rb  = *(const float2*)(rp + 2);
        float2 rc2 = *(const float2*)(rp + 4);

        float pR = warpSum1(w0 * ra.x + w1 * rb.y);
        float pG = warpSum1(w0 * ra.y + w1 * rc2.x);
        float pB = warpSum1(w0 * rb.x + w1 * rc2.y);
        float pW = warpSum1(w0 + w1);
        float pD = warpSum1(w0 * z0 + w1 * z1);
        if (lane < 16) {
            osm[w][0   + lane] = pR;   // q0 accR
            osm[w][16  + lane] = pG;   // q1 accG
            osm[w][32  + lane] = pB;   // q2 accB
            osm[w][48  + lane] = pW;   // q3 wsum
            osm[w][64  + lane] = pD;   // q4 dep
        }
        if (lane == 0) osm[w][160] = fr;

        // ---- cdf over weights[1..62] + 1e-5: registers, 2 entries/lane ----
        float t0c = (s0 >= 1)  ? (w0 + 1e-5f) : 0.0f;
        float t1c = (s1 <= 62) ? (w1 + 1e-5f) : 0.0f;
        float incl = warpInclSum(t0c + t1c, lane);
        float totw = __shfl_sync(FULLMASK, incl, 31);
        float exS  = __shfl_up_sync(FULLMASK, incl, 1);
        if (lane == 0) exS = 0.0f;
        float inv = 1.0f / totw;
        float cdfE = (exS + t0c) * inv;
        float cdfO = (lane == 31) ? 3.0e38f : (incl * inv);

        // ============== fine z: inverse CDF via shuffle search, j = 2l, 2l+1 =========
        float zfine[2];
        int   cfin[2];   // c_j ≈ #{z_coarse <= z_fine_j} (analytic; monotonized below)
        #pragma unroll
        for (int q = 0; q < 2; q++) {
            int j = 2 * lane + q;
            float u = (j == 63) ? 1.0f : (float)j * (1.0f / 63.0f);

            // ind = searchsorted(cdf[0..62], u, 'right')
            int ne = cntLE_f(cdfE, u);                       // in [1,32]
            float oprev = __shfl_sync(FULLMASK, cdfO, ne - 1);
            int t = (oprev <= u) ? 1 : 0;
            int ind = 2 * ne - 1 + t;                        // in [1,63]
            float eprev = __shfl_sync(FULLMASK, cdfE, ne - 1);
            float enext = __shfl_sync(FULLMASK, cdfE, min(ne, 31));

            int below = ind - 1;
            int above = ind < 62 ? ind : 62;
            float cb = t ? oprev : eprev;
            float ca = (t || ind == 63) ? enext : oprev;

            float bb = nr + ((float)below + 0.5f) * dzs;     // bin midpoints
            float ba = nr + ((float)above + 0.5f) * dzs;
            float den = ca - cb;
            if (den < 1e-5f) den = 1.0f;
            float zf = bb + __fdividef(u - cb, den) * (ba - bb);
            zfine[q] = zf;

            // analytic coarse-count; ties resolved by the monotonize pass
            int c = (int)((zf - nr) * invstep) + 1;
            cfin[q] = max(0, min(64, c));
        }

        // ============== monotonize c (running max) — makes the merge a bijection ====
        int c0 = cfin[0], c1 = cfin[1];
        {
            int hi = max(c0, c1);
            int scan = hi;
            #pragma unroll
            for (int d = 1; d < 32; d <<= 1) {
                int o = __shfl_up_sync(FULLMASK, scan, d);
                if (lane >= d) scan = max(scan, o);
            }
            int ex = __shfl_up_sync(FULLMASK, scan, 1);
            if (lane == 0) ex = 0;
            c0 = max(ex, c0);
            c1 = max(c0, c1);
        }
        ZM[2 * lane + c0]     = zfine[0];      // fine merged position = j + c'_j
        ZM[2 * lane + 1 + c1] = zfine[1];

        // ============== coarse merged positions via duality on c' ==============
        #pragma unroll
        for (int q = 0; q < 2; q++) {
            int i = 2 * lane + q;
            int ne = cntLE_i(c0, i);                        // in [0,32]
            int src = ne > 0 ? ne - 1 : 0;
            int cprev = __shfl_sync(FULLMASK, c1, src);
            int cnt = ne > 0 ? (2 * ne - 1 + (cprev <= i ? 1 : 0)) : 0;
            ZM[i + cnt] = (q == 0) ? z0 : z1;
        }
        __syncwarp();

        // ============== fine composite: lane handles samples 4l..4l+3 ==============
        float4 zq = *(const float4*)&ZM[4 * lane];
        float zn  = (lane == 31) ? 0.0f : ZM[4 * lane + 4];
        float dd0 = zq.y - zq.x;
        float dd1 = zq.z - zq.y;
        float dd2 = zq.w - zq.z;
        float dd3 = (lane == 31) ? 1e10f : (zn - zq.w);

        float ee0 = __expf(-dd0 * fmaxf(sg4.x, 0.0f));
        float ee1 = __expf(-dd1 * fmaxf(sg4.y, 0.0f));
        float ee2 = __expf(-dd2 * fmaxf(sg4.z, 0.0f));
        float ee3 = __expf(-dd3 * fmaxf(sg4.w, 0.0f));
        float fa0 = 1.0f - ee0, fa1 = 1.0f - ee1, fa2 = 1.0f - ee2, fa3 = 1.0f - ee3;
        float ff0 = ee0 + 1e-10f, ff1 = ee1 + 1e-10f, ff2 = ee2 + 1e-10f, ff3 = ee3 + 1e-10f;

        float E2 = warpExclProd(ff0 * ff1 * ff2 * ff3, lane);
        float U0 = E2, U1 = U0 * ff0, U2 = U1 * ff1, U3 = U2 * ff2;
        float v0 = fa0 * U0, v1 = fa1 * U1, v2 = fa2 * U2, v3 = fa3 * U3;

        float pFR = warpSum1(v0 * q0.x + v1 * q0.w + v2 * q1.z + v3 * q2.y);
        float pFG = warpSum1(v0 * q0.y + v1 * q1.x + v2 * q1.w + v3 * q2.z);
        float pFB = warpSum1(v0 * q0.z + v1 * q1.y + v2 * q2.x + v3 * q2.w);
        float pFW = warpSum1(v0 + v1 + v2 + v3);
        float pFD = warpSum1(v0 * zq.x + v1 * zq.y + v2 * zq.z + v3 * zq.w);
        if (lane < 16) {
            osm[w][80  + lane] = pFR;  // q5 fR
            osm[w][96  + lane] = pFG;  // q6 fG
            osm[w][112 + lane] = pFB;  // q7 fB
            osm[w][128 + lane] = pFW;  // q8 wsF
            osm[w][144 + lane] = pFD;  // q9 depF
        }
    }
    __syncthreads();

    // ============== output phase: finish reductions + coalesced writes ==============
    const int t = threadIdx.x;
    const size_t R0 = (size_t)blockIdx.x * WPB;
    const int nblk = min(WPB, N - (int)R0);
    const size_t NN = (size_t)N;

    #define SUMQ(r, q) ({ const float4* _b = (const float4*)&osm[(r)][16 * (q)]; \
                          float4 _p0 = _b[0], _p1 = _b[1], _p2 = _b[2], _p3 = _b[3]; \
                          (((_p0.x + _p0.y) + (_p0.z + _p0.w)) +                 \
                           ((_p1.x + _p1.y) + (_p1.z + _p1.w))) +                \
                          (((_p2.x + _p2.y) + (_p2.z + _p2.w)) +                 \
                           ((_p3.x + _p3.y) + (_p3.z + _p3.w))); })

    if (t < 24) {                               // coarse rgb
        int r = t / 3, c = t % 3;
        if (r < nblk) out[3 * R0 + t] = SUMQ(r, c) + 1.0f - SUMQ(r, 3);
    } else if (t < 32) {                        // coarse alpha (weights_sum)
        int r = t - 24;
        if (r < nblk) out[3 * NN + R0 + r] = SUMQ(r, 3);
    } else if (t < 40) {                        // coarse depth
        int r = t - 32;
        if (r < nblk) out[4 * NN + R0 + r] = SUMQ(r, 4) + (1.0f - SUMQ(r, 3)) * osm[r][160];
    } else if (t < 64) {                        // fine rgb
        int j = t - 40;
        int r = j / 3, c = j % 3;
        if (r < nblk) out[5 * NN + 3 * R0 + j] = SUMQ(r, 5 + c) + 1.0f - SUMQ(r, 8);
    } else if (t < 72) {                        // fine alpha
        int r = t - 64;
        if (r < nblk) out[8 * NN + R0 + r] = SUMQ(r, 8);
    } else if (t < 80) {                        // fine depth
        int r = t - 72;
        if (r < nblk) out[9 * NN + R0 + r] = SUMQ(r, 9) + (1.0f - SUMQ(r, 8)) * osm[r][160];
    }
    #undef SUMQ
}

extern "C" void kernel_launch(void* const* d_in, const int* in_sizes, int n_in,
                              void* d_out, int out_size) {
    const float* rays = (const float*)d_in[0];
    const float* sc   = (const float*)d_in[1];
    const float* rc   = (const float*)d_in[2];
    const float* sf   = (const float*)d_in[3];
    const float* rf   = (const float*)d_in[4];
    float* out = (float*)d_out;
    int N = in_sizes[0] / 8;
    int blocks = (N + WPB - 1) / WPB;
    nerf_kernel<<<blocks, WPB * 32>>>(rays, sc, rc, sf, rf, out, N);
}

// round 15
// speedup vs baseline: 1.0727x; 1.0341x over previous
#include <cuda_runtime.h>

#define FULLMASK 0xffffffffu
#define WPB 8   // warps (rays) per block

__device__ __forceinline__ float warpExclProd(float p, int lane) {
    float incl = p;
    #pragma unroll
    for (int d = 1; d < 32; d <<= 1) {
        float o = __shfl_up_sync(FULLMASK, incl, d);
        if (lane >= d) incl *= o;
    }
    float excl = __shfl_up_sync(FULLMASK, incl, 1);
    if (lane == 0) excl = 1.0f;
    return excl;
}

__device__ __forceinline__ float warpInclSum(float v, int lane) {
    #pragma unroll
    for (int d = 1; d < 32; d <<= 1) {
        float o = __shfl_up_sync(FULLMASK, v, d);
        if (lane >= d) v += o;
    }
    return v;
}

// 1-stage partial reduction: lane l holds v_l + v_{l^16}. Lanes 0..15 stage 16
// partials; the final add happens in the (otherwise idle) output phase.
__device__ __forceinline__ float warpSum1(float v) {
    return v + __shfl_xor_sync(FULLMASK, v, 16);
}

// #{l in [0,32) : E_l <= u} for a sorted lane-distributed float array.
// 5 bisection probes + 1 final probe (33 outcomes need 6 comparisons).
__device__ __forceinline__ int cntLE_f(float E, float u) {
    int lo = 0;
    #pragma unroll
    for (int s = 16; s; s >>= 1) {
        float v = __shfl_sync(FULLMASK, E, lo + s - 1);
        if (v <= u) lo += s;
    }
    float v = __shfl_sync(FULLMASK, E, lo);
    if (v <= u) lo += 1;
    return lo;
}

// same for a sorted lane-distributed int array
__device__ __forceinline__ int cntLE_i(int E, int u) {
    int lo = 0;
    #pragma unroll
    for (int s = 16; s; s >>= 1) {
        int v = __shfl_sync(FULLMASK, E, lo + s - 1);
        if (v <= u) lo += s;
    }
    int v = __shfl_sync(FULLMASK, E, lo);
    if (v <= u) lo += 1;
    return lo;
}

__global__ void __launch_bounds__(WPB * 32, 8)
nerf_kernel(const float* __restrict__ rays,
            const float* __restrict__ sigc,
            const float* __restrict__ rgbc,
            const float* __restrict__ sigf,
            const float* __restrict__ rgbf,
            float* __restrict__ out,
            int N)
{
    __shared__ __align__(16) float smem[WPB][128];   // merged z
    __shared__ __align__(16) float osm[WPB][164];    // 10 q's x 16 partials + fr
    const int lane = threadIdx.x & 31;
    const int w    = threadIdx.x >> 5;
    const int ray  = blockIdx.x * WPB + w;

    if (ray < N) {
        float* ZM = smem[w];          // 128 merged z

        float2 nf = *(const float2*)(rays + (size_t)ray * 8 + 6);
        const float nr = nf.x, fr = nf.y;
        const float dzs = (fr - nr) * 0.015625f;     // (far-near)/64
        const float invstep = 1.0f / dzs;

        // ============== coarse pass: lane handles samples 2l, 2l+1 ==============
        const int s0 = lane * 2, s1 = s0 + 1;
        float z0 = nr + (float)s0 * dzs;
        float z1 = nr + (float)s1 * dzs;
        // coarse grid is uniform: delta == dzs exactly (ulp-level vs subtraction)
        float d0 = dzs;
        float d1 = (lane == 31) ? 1e10f : dzs;

        float2 sg = *(const float2*)(sigc + (size_t)ray * 64 + s0);
        float e0 = __expf(-d0 * fmaxf(sg.x, 0.0f));
        float e1 = __expf(-d1 * fmaxf(sg.y, 0.0f));
        float a0 = 1.0f - e0, a1 = 1.0f - e1;
        float f0 = e0 + 1e-10f, f1 = e1 + 1e-10f;

        float E  = warpExclProd(f0 * f1, lane);
        float T0 = E, T1 = E * f0;
        float w0 = a0 * T0, w1 = a1 * T1;

        const float* rp = rgbc + (size_t)ray * 192 + lane * 6;
        float2 ra  = *(const float2*)(rp);
        float2 rb  = *(const float2*)(rp + 2);
        float2 rc2 = *(const float2*)(rp + 4);

        float pR = warpSum1(w0 * ra.x + w1 * rb.y);
        float pG = warpSum1(w0 * ra.y + w1 * rc2.x);
        float pB = warpSum1(w0 * rb.x + w1 * rc2.y);
        float pW = warpSum1(w0 + w1);
        float pD = warpSum1(w0 * z0 + w1 * z1);
        if (lane < 16) {
            osm[w][0   + lane] = pR;   // q0 accR
            osm[w][16  + lane] = pG;   // q1 accG
            osm[w][32  + lane] = pB;   // q2 accB
            osm[w][48  + lane] = pW;   // q3 wsum
            osm[w][64  + lane] = pD;   // q4 dep
        }
        if (lane == 0) osm[w][160] = fr;

        // ---- cdf over weights[1..62] + 1e-5: registers, 2 entries/lane ----
        float t0c = (s0 >= 1)  ? (w0 + 1e-5f) : 0.0f;
        float t1c = (s1 <= 62) ? (w1 + 1e-5f) : 0.0f;
        float incl = warpInclSum(t0c + t1c, lane);
        float totw = __shfl_sync(FULLMASK, incl, 31);
        float exS  = __shfl_up_sync(FULLMASK, incl, 1);
        if (lane == 0) exS = 0.0f;
        float inv = 1.0f / totw;
        float cdfE = (exS + t0c) * inv;
        float cdfO = (lane == 31) ? 3.0e38f : (incl * inv);

        // ============== fine z: inverse CDF via shuffle search, j = 2l, 2l+1 =========
        float zfine[2];
        int   cfin[2];   // c_j ≈ #{z_coarse <= z_fine_j} (analytic; monotonized below)
        #pragma unroll
        for (int q = 0; q < 2; q++) {
            int j = 2 * lane + q;
            float u = (j == 63) ? 1.0f : (float)j * (1.0f / 63.0f);

            // ind = searchsorted(cdf[0..62], u, 'right')
            int ne = cntLE_f(cdfE, u);                       // in [1,32]
            float oprev = __shfl_sync(FULLMASK, cdfO, ne - 1);
            int t = (oprev <= u) ? 1 : 0;
            int ind = 2 * ne - 1 + t;                        // in [1,63]
            float eprev = __shfl_sync(FULLMASK, cdfE, ne - 1);
            float enext = __shfl_sync(FULLMASK, cdfE, min(ne, 31));

            int below = ind - 1;
            int above = ind < 62 ? ind : 62;
            float cb = t ? oprev : eprev;
            float ca = (t || ind == 63) ? enext : oprev;

            float bb = nr + ((float)below + 0.5f) * dzs;     // bin midpoints
            float ba = nr + ((float)above + 0.5f) * dzs;
            float den = ca - cb;
            if (den < 1e-5f) den = 1.0f;
            float zf = bb + __fdividef(u - cb, den) * (ba - bb);
            zfine[q] = zf;

            // analytic coarse-count; ties resolved by the monotonize pass
            int c = (int)((zf - nr) * invstep) + 1;
            cfin[q] = max(0, min(64, c));
        }

        // ============== monotonize c (running max) — makes the merge a bijection ====
        int c0 = cfin[0], c1 = cfin[1];
        {
            int hi = max(c0, c1);
            int scan = hi;
            #pragma unroll
            for (int d = 1; d < 32; d <<= 1) {
                int o = __shfl_up_sync(FULLMASK, scan, d);
                if (lane >= d) scan = max(scan, o);
            }
            int ex = __shfl_up_sync(FULLMASK, scan, 1);
            if (lane == 0) ex = 0;
            c0 = max(ex, c0);
            c1 = max(c0, c1);
        }
        ZM[2 * lane + c0]     = zfine[0];      // fine merged position = j + c'_j
        ZM[2 * lane + 1 + c1] = zfine[1];

        // ============== coarse merged positions via duality on c' ==============
        #pragma unroll
        for (int q = 0; q < 2; q++) {
            int i = 2 * lane + q;
            int ne = cntLE_i(c0, i);                        // in [0,32]
            int src = ne > 0 ? ne - 1 : 0;
            int cprev = __shfl_sync(FULLMASK, c1, src);
            int cnt = ne > 0 ? (2 * ne - 1 + (cprev <= i ? 1 : 0)) : 0;
            ZM[i + cnt] = (q == 0) ? z0 : z1;
        }
        __syncwarp();

        // ============== fine composite: lane handles samples 4l..4l+3 ==============
        float4 zq = *(const float4*)&ZM[4 * lane];
        float zn  = (lane == 31) ? 0.0f : ZM[4 * lane + 4];
        float dd0 = zq.y - zq.x;
        float dd1 = zq.z - zq.y;
        float dd2 = zq.w - zq.z;
        float dd3 = (lane == 31) ? 1e10f : (zn - zq.w);

        float4 sg4 = *(const float4*)(sigf + (size_t)ray * 128 + 4 * lane);
        float ee0 = __expf(-dd0 * fmaxf(sg4.x, 0.0f));
        float ee1 = __expf(-dd1 * fmaxf(sg4.y, 0.0f));
        float ee2 = __expf(-dd2 * fmaxf(sg4.z, 0.0f));
        float ee3 = __expf(-dd3 * fmaxf(sg4.w, 0.0f));
        float fa0 = 1.0f - ee0, fa1 = 1.0f - ee1, fa2 = 1.0f - ee2, fa3 = 1.0f - ee3;
        float ff0 = ee0 + 1e-10f, ff1 = ee1 + 1e-10f, ff2 = ee2 + 1e-10f, ff3 = ee3 + 1e-10f;

        float E2 = warpExclProd(ff0 * ff1 * ff2 * ff3, lane);
        float U0 = E2, U1 = U0 * ff0, U2 = U1 * ff1, U3 = U2 * ff2;
        float v0 = fa0 * U0, v1 = fa1 * U1, v2 = fa2 * U2, v3 = fa3 * U3;

        const float* rfp = rgbf + (size_t)ray * 384 + 12 * lane;
        float4 q0 = *(const float4*)(rfp);
        float4 q1 = *(const float4*)(rfp + 4);
        float4 q2 = *(const float4*)(rfp + 8);

        float pFR = warpSum1(v0 * q0.x + v1 * q0.w + v2 * q1.z + v3 * q2.y);
        float pFG = warpSum1(v0 * q0.y + v1 * q1.x + v2 * q1.w + v3 * q2.z);
        float pFB = warpSum1(v0 * q0.z + v1 * q1.y + v2 * q2.x + v3 * q2.w);
        float pFW = warpSum1(v0 + v1 + v2 + v3);
        float pFD = warpSum1(v0 * zq.x + v1 * zq.y + v2 * zq.z + v3 * zq.w);
        if (lane < 16) {
            osm[w][80  + lane] = pFR;  // q5 fR
            osm[w][96  + lane] = pFG;  // q6 fG
            osm[w][112 + lane] = pFB;  // q7 fB
            osm[w][128 + lane] = pFW;  // q8 wsF
            osm[w][144 + lane] = pFD;  // q9 depF
        }
    }
    __syncthreads();

    // ============== output phase: finish reductions + coalesced writes ==============
    const int t = threadIdx.x;
    const size_t R0 = (size_t)blockIdx.x * WPB;
    const int nblk = min(WPB, N - (int)R0);
    const size_t NN = (size_t)N;

    #define SUMQ(r, q) ({ const float4* _b = (const float4*)&osm[(r)][16 * (q)]; \
                          float4 _p0 = _b[0], _p1 = _b[1], _p2 = _b[2], _p3 = _b[3]; \
                          (((_p0.x + _p0.y) + (_p0.z + _p0.w)) +                 \
                           ((_p1.x + _p1.y) + (_p1.z + _p1.w))) +                \
                          (((_p2.x + _p2.y) + (_p2.z + _p2.w)) +                 \
                           ((_p3.x + _p3.y) + (_p3.z + _p3.w))); })

    if (t < 24) {                               // coarse rgb
        int r = t / 3, c = t % 3;
        if (r < nblk) out[3 * R0 + t] = SUMQ(r, c) + 1.0f - SUMQ(r, 3);
    } else if (t < 32) {                        // coarse alpha (weights_sum)
        int r = t - 24;
        if (r < nblk) out[3 * NN + R0 + r] = SUMQ(r, 3);
    } else if (t < 40) {                        // coarse depth
        int r = t - 32;
        if (r < nblk) out[4 * NN + R0 + r] = SUMQ(r, 4) + (1.0f - SUMQ(r, 3)) * osm[r][160];
    } else if (t < 64) {                        // fine rgb
        int j = t - 40;
        int r = j / 3, c = j % 3;
        if (r < nblk) out[5 * NN + 3 * R0 + j] = SUMQ(r, 5 + c) + 1.0f - SUMQ(r, 8);
    } else if (t < 72) {                        // fine alpha
        int r = t - 64;
        if (r < nblk) out[8 * NN + R0 + r] = SUMQ(r, 8);
    } else if (t < 80) {                        // fine depth
        int r = t - 72;
        if (r < nblk) out[9 * NN + R0 + r] = SUMQ(r, 9) + (1.0f - SUMQ(r, 8)) * osm[r][160];
    }
    #undef SUMQ
}

extern "C" void kernel_launch(void* const* d_in, const int* in_sizes, int n_in,
                              void* d_out, int out_size) {
    const float* rays = (const float*)d_in[0];
    const float* sc   = (const float*)d_in[1];
    const float* rc   = (const float*)d_in[2];
    const float* sf   = (const float*)d_in[3];
    const float* rf   = (const float*)d_in[4];
    float* out = (float*)d_out;
    int N = in_sizes[0] / 8;
    int blocks = (N + WPB - 1) / WPB;
    nerf_kernel<<<blocks, WPB * 32>>>(rays, sc, rc, sf, rf, out, N);
}

// round 16
// speedup vs baseline: 1.0960x; 1.0217x over previous
#include <cuda_runtime.h>

#define FULLMASK 0xffffffffu
#define WPB 8   // warps (rays) per block

__device__ __forceinline__ float warpExclProd(float p, int lane) {
    float incl = p;
    #pragma unroll
    for (int d = 1; d < 32; d <<= 1) {
        float o = __shfl_up_sync(FULLMASK, incl, d);
        if (lane >= d) incl *= o;
    }
    float excl = __shfl_up_sync(FULLMASK, incl, 1);
    if (lane == 0) excl = 1.0f;
    return excl;
}

__device__ __forceinline__ float warpInclSum(float v, int lane) {
    #pragma unroll
    for (int d = 1; d < 32; d <<= 1) {
        float o = __shfl_up_sync(FULLMASK, v, d);
        if (lane >= d) v += o;
    }
    return v;
}

// 1-stage partial reduction: lane l holds v_l + v_{l^16}. Lanes 0..15 stage 16
// partials; the final add happens in the (otherwise idle) output phase.
__device__ __forceinline__ float warpSum1(float v) {
    return v + __shfl_xor_sync(FULLMASK, v, 16);
}

// #{l in [0,32) : E_l <= u} for a sorted lane-distributed float array.
// 5 bisection probes + 1 final probe (33 outcomes need 6 comparisons).
__device__ __forceinline__ int cntLE_f(float E, float u) {
    int lo = 0;
    #pragma unroll
    for (int s = 16; s; s >>= 1) {
        float v = __shfl_sync(FULLMASK, E, lo + s - 1);
        if (v <= u) lo += s;
    }
    float v = __shfl_sync(FULLMASK, E, lo);
    if (v <= u) lo += 1;
    return lo;
}

// same for a sorted lane-distributed int array
__device__ __forceinline__ int cntLE_i(int E, int u) {
    int lo = 0;
    #pragma unroll
    for (int s = 16; s; s >>= 1) {
        int v = __shfl_sync(FULLMASK, E, lo + s - 1);
        if (v <= u) lo += s;
    }
    int v = __shfl_sync(FULLMASK, E, lo);
    if (v <= u) lo += 1;
    return lo;
}

__global__ void __launch_bounds__(WPB * 32, 8)
nerf_kernel(const float* __restrict__ rays,
            const float* __restrict__ sigc,
            const float* __restrict__ rgbc,
            const float* __restrict__ sigf,
            const float* __restrict__ rgbf,
            float* __restrict__ out,
            int N)
{
    __shared__ __align__(16) float smem[WPB][128];   // merged z
    __shared__ __align__(16) float osm[WPB][164];    // 9 q's x 16 partials + fr + wsum
    const int lane = threadIdx.x & 31;
    const int w    = threadIdx.x >> 5;
    const int ray  = blockIdx.x * WPB + w;

    if (ray < N) {
        float* ZM = smem[w];          // 128 merged z

        float2 nf = *(const float2*)(rays + (size_t)ray * 8 + 6);
        const float nr = nf.x, fr = nf.y;
        const float dzs = (fr - nr) * 0.015625f;     // (far-near)/64
        const float invstep = 1.0f / dzs;

        // ============== coarse pass: lane handles samples 2l, 2l+1 ==============
        const int s0 = lane * 2, s1 = s0 + 1;
        float z0 = nr + (float)s0 * dzs;
        float z1 = nr + (float)s1 * dzs;

        // exp(-d*s) = exp2((-d*log2e)*s); -d*log2e pre-folded (d uniform = dzs)
        const float ndl2  = dzs * -1.442695041f;
        const float ndl2b = (lane == 31) ? -1.442695041e10f : ndl2;  // delta_inf

        float2 sg = *(const float2*)(sigc + (size_t)ray * 64 + s0);
        float e0 = exp2f(ndl2  * fmaxf(sg.x, 0.0f));
        float e1 = exp2f(ndl2b * fmaxf(sg.y, 0.0f));
        float a0 = 1.0f - e0, a1 = 1.0f - e1;
        float f0 = e0 + 1e-10f, f1 = e1 + 1e-10f;

        float E  = warpExclProd(f0 * f1, lane);
        float T0 = E, T1 = E * f0;
        float w0 = a0 * T0, w1 = a1 * T1;

        const float* rp = rgbc + (size_t)ray * 192 + lane * 6;
        float2 ra  = *(const float2*)(rp);
        float2 rb  = *(const float2*)(rp + 2);
        float2 rc2 = *(const float2*)(rp + 4);

        float pR = warpSum1(w0 * ra.x + w1 * rb.y);
        float pG = warpSum1(w0 * ra.y + w1 * rc2.x);
        float pB = warpSum1(w0 * rb.x + w1 * rc2.y);
        float pD = warpSum1(w0 * z0 + w1 * z1);
        if (lane < 16) {
            osm[w][0   + lane] = pR;   // q0 accR
            osm[w][16  + lane] = pG;   // q1 accG
            osm[w][32  + lane] = pB;   // q2 accB
            osm[w][64  + lane] = pD;   // q4 dep
        }
        if (lane == 0) osm[w][160] = fr;

        // ---- cdf over weights[1..62] + 1e-5: registers, 2 entries/lane ----
        float t0c = (s0 >= 1)  ? (w0 + 1e-5f) : 0.0f;
        float t1c = (s1 <= 62) ? (w1 + 1e-5f) : 0.0f;
        float incl = warpInclSum(t0c + t1c, lane);
        float totw = __shfl_sync(FULLMASK, incl, 31);
        float exS  = __shfl_up_sync(FULLMASK, incl, 1);
        if (lane == 0) exS = 0.0f;
        float inv = 1.0f / totw;
        float cdfE = (exS + t0c) * inv;
        float cdfO = (lane == 31) ? 3.0e38f : (incl * inv);

        // wsum = sum(all 64 weights) = (totw - 62*1e-5) + w[0] + w[63]
        {
            float w00  = __shfl_sync(FULLMASK, w0, 0);
            float w631 = __shfl_sync(FULLMASK, w1, 31);
            if (lane == 0)
                osm[w][161] = (totw - 62.0f * 1e-5f) + w00 + w631;
        }

        // ============== fine z: inverse CDF via shuffle search, j = 2l, 2l+1 =========
        float zfine[2];
        int   cfin[2];   // c_j ≈ #{z_coarse <= z_fine_j} (analytic; monotonized below)
        #pragma unroll
        for (int q = 0; q < 2; q++) {
            int j = 2 * lane + q;
            float u = (j == 63) ? 1.0f : (float)j * (1.0f / 63.0f);

            // ind = searchsorted(cdf[0..62], u, 'right')
            int ne = cntLE_f(cdfE, u);                       // in [1,32]
            float oprev = __shfl_sync(FULLMASK, cdfO, ne - 1);
            int t = (oprev <= u) ? 1 : 0;
            int ind = 2 * ne - 1 + t;                        // in [1,63]
            float eprev = __shfl_sync(FULLMASK, cdfE, ne - 1);
            float enext = __shfl_sync(FULLMASK, cdfE, min(ne, 31));

            int below = ind - 1;
            int above = ind < 62 ? ind : 62;
            float cb = t ? oprev : eprev;
            float ca = (t || ind == 63) ? enext : oprev;

            float bb = nr + ((float)below + 0.5f) * dzs;     // bin midpoints
            float ba = nr + ((float)above + 0.5f) * dzs;
            float den = ca - cb;
            if (den < 1e-5f) den = 1.0f;
            float zf = bb + __fdividef(u - cb, den) * (ba - bb);
            zfine[q] = zf;

            // analytic coarse-count; ties resolved by the monotonize pass
            int c = (int)((zf - nr) * invstep) + 1;
            cfin[q] = max(0, min(64, c));
        }

        // ============== monotonize c (running max) — makes the merge a bijection ====
        int c0 = cfin[0], c1 = cfin[1];
        {
            int hi = max(c0, c1);
            int scan = hi;
            #pragma unroll
            for (int d = 1; d < 32; d <<= 1) {
                int o = __shfl_up_sync(FULLMASK, scan, d);
                if (lane >= d) scan = max(scan, o);
            }
            int ex = __shfl_up_sync(FULLMASK, scan, 1);
            if (lane == 0) ex = 0;
            c0 = max(ex, c0);
            c1 = max(c0, c1);
        }
        ZM[2 * lane + c0]     = zfine[0];      // fine merged position = j + c'_j
        ZM[2 * lane + 1 + c1] = zfine[1];

        // ============== coarse merged positions via duality on c' ==============
        #pragma unroll
        for (int q = 0; q < 2; q++) {
            int i = 2 * lane + q;
            int ne = cntLE_i(c0, i);                        // in [0,32]
            int src = ne > 0 ? ne - 1 : 0;
            int cprev = __shfl_sync(FULLMASK, c1, src);
            int cnt = ne > 0 ? (2 * ne - 1 + (cprev <= i ? 1 : 0)) : 0;
            ZM[i + cnt] = (q == 0) ? z0 : z1;
        }
        __syncwarp();

        // ============== fine composite: lane handles samples 4l..4l+3 ==============
        float4 zq = *(const float4*)&ZM[4 * lane];
        float zn  = __shfl_down_sync(FULLMASK, zq.x, 1);   // ZM[4l+4] = lane l+1's zq.x
        float dd0 = zq.y - zq.x;
        float dd1 = zq.z - zq.y;
        float dd2 = zq.w - zq.z;
        float dd3 = (lane == 31) ? 1e10f : (zn - zq.w);

        float4 sg4 = *(const float4*)(sigf + (size_t)ray * 128 + 4 * lane);
        float ee0 = __expf(-dd0 * fmaxf(sg4.x, 0.0f));
        float ee1 = __expf(-dd1 * fmaxf(sg4.y, 0.0f));
        float ee2 = __expf(-dd2 * fmaxf(sg4.z, 0.0f));
        float ee3 = __expf(-dd3 * fmaxf(sg4.w, 0.0f));
        float fa0 = 1.0f - ee0, fa1 = 1.0f - ee1, fa2 = 1.0f - ee2, fa3 = 1.0f - ee3;
        float ff0 = ee0 + 1e-10f, ff1 = ee1 + 1e-10f, ff2 = ee2 + 1e-10f, ff3 = ee3 + 1e-10f;

        float E2 = warpExclProd(ff0 * ff1 * ff2 * ff3, lane);
        float U0 = E2, U1 = U0 * ff0, U2 = U1 * ff1, U3 = U2 * ff2;
        float v0 = fa0 * U0, v1 = fa1 * U1, v2 = fa2 * U2, v3 = fa3 * U3;

        const float* rfp = rgbf + (size_t)ray * 384 + 12 * lane;
        float4 q0 = *(const float4*)(rfp);
        float4 q1 = *(const float4*)(rfp + 4);
        float4 q2 = *(const float4*)(rfp + 8);

        float pFR = warpSum1(v0 * q0.x + v1 * q0.w + v2 * q1.z + v3 * q2.y);
        float pFG = warpSum1(v0 * q0.y + v1 * q1.x + v2 * q1.w + v3 * q2.z);
        float pFB = warpSum1(v0 * q0.z + v1 * q1.y + v2 * q2.x + v3 * q2.w);
        float pFW = warpSum1(v0 + v1 + v2 + v3);
        float pFD = warpSum1(v0 * zq.x + v1 * zq.y + v2 * zq.z + v3 * zq.w);
        if (lane < 16) {
            osm[w][80  + lane] = pFR;  // q5 fR
            osm[w][96  + lane] = pFG;  // q6 fG
            osm[w][112 + lane] = pFB;  // q7 fB
            osm[w][128 + lane] = pFW;  // q8 wsF
            osm[w][144 + lane] = pFD;  // q9 depF
        }
    }
    __syncthreads();

    // ============== output phase: finish reductions + coalesced writes ==============
    const int t = threadIdx.x;
    const size_t R0 = (size_t)blockIdx.x * WPB;
    const int nblk = min(WPB, N - (int)R0);
    const size_t NN = (size_t)N;

    #define SUMQ(r, q) ({ const float4* _b = (const float4*)&osm[(r)][16 * (q)]; \
                          float4 _p0 = _b[0], _p1 = _b[1], _p2 = _b[2], _p3 = _b[3]; \
                          (((_p0.x + _p0.y) + (_p0.z + _p0.w)) +                 \
                           ((_p1.x + _p1.y) + (_p1.z + _p1.w))) +                \
                          (((_p2.x + _p2.y) + (_p2.z + _p2.w)) +                 \
                           ((_p3.x + _p3.y) + (_p3.z + _p3.w))); })

    if (t < 24) {                               // coarse rgb
        int r = t / 3, c = t % 3;
        if (r < nblk) out[3 * R0 + t] = SUMQ(r, c) + 1.0f - osm[r][161];
    } else if (t < 32) {                        // coarse alpha (weights_sum)
        int r = t - 24;
        if (r < nblk) out[3 * NN + R0 + r] = osm[r][161];
    } else if (t < 40) {                        // coarse depth
        int r = t - 32;
        if (r < nblk) out[4 * NN + R0 + r] = SUMQ(r, 4) + (1.0f - osm[r][161]) * osm[r][160];
    } else if (t < 64) {                        // fine rgb
        int j = t - 40;
        int r = j / 3, c = j % 3;
        if (r < nblk) out[5 * NN + 3 * R0 + j] = SUMQ(r, 5 + c) + 1.0f - SUMQ(r, 8);
    } else if (t < 72) {                        // fine alpha
        int r = t - 64;
        if (r < nblk) out[8 * NN + R0 + r] = SUMQ(r, 8);
    } else if (t < 80) {                        // fine depth
        int r = t - 72;
        if (r < nblk) out[9 * NN + R0 + r] = SUMQ(r, 9) + (1.0f - SUMQ(r, 8)) * osm[r][160];
    }
    #undef SUMQ
}

extern "C" void kernel_launch(void* const* d_in, const int* in_sizes, int n_in,
                              void* d_out, int out_size) {
    const float* rays = (const float*)d_in[0];
    const float* sc   = (const float*)d_in[1];
    const float* rc   = (const float*)d_in[2];
    const float* sf   = (const float*)d_in[3];
    const float* rf   = (const float*)d_in[4];
    float* out = (float*)d_out;
    int N = in_sizes[0] / 8;
    int blocks = (N + WPB - 1) / WPB;
    nerf_kernel<<<blocks, WPB * 32>>>(rays, sc, rc, sf, rf, out, N);
}

// round 17
// speedup vs baseline: 1.0994x; 1.0031x over previous
#include <cuda_runtime.h>

#define FULLMASK 0xffffffffu
#define WPB 8   // warps (rays) per block

__device__ __forceinline__ float warpExclProd(float p, int lane) {
    float incl = p;
    #pragma unroll
    for (int d = 1; d < 32; d <<= 1) {
        float o = __shfl_up_sync(FULLMASK, incl, d);
        if (lane >= d) incl *= o;
    }
    float excl = __shfl_up_sync(FULLMASK, incl, 1);
    if (lane == 0) excl = 1.0f;
    return excl;
}

__device__ __forceinline__ float warpInclSum(float v, int lane) {
    #pragma unroll
    for (int d = 1; d < 32; d <<= 1) {
        float o = __shfl_up_sync(FULLMASK, v, d);
        if (lane >= d) v += o;
    }
    return v;
}

// 1-stage partial reduction: lane l holds v_l + v_{l^16}. Lanes 0..15 stage 16
// partials; the final add happens in the (otherwise idle) output phase.
__device__ __forceinline__ float warpSum1(float v) {
    return v + __shfl_xor_sync(FULLMASK, v, 16);
}

// #{l in [0,32) : E_l <= u} for a sorted lane-distributed float array.
// 5 bisection probes + 1 final probe (33 outcomes need 6 comparisons).
__device__ __forceinline__ int cntLE_f(float E, float u) {
    int lo = 0;
    #pragma unroll
    for (int s = 16; s; s >>= 1) {
        float v = __shfl_sync(FULLMASK, E, lo + s - 1);
        if (v <= u) lo += s;
    }
    float v = __shfl_sync(FULLMASK, E, lo);
    if (v <= u) lo += 1;
    return lo;
}

// same for a sorted lane-distributed int array
__device__ __forceinline__ int cntLE_i(int E, int u) {
    int lo = 0;
    #pragma unroll
    for (int s = 16; s; s >>= 1) {
        int v = __shfl_sync(FULLMASK, E, lo + s - 1);
        if (v <= u) lo += s;
    }
    int v = __shfl_sync(FULLMASK, E, lo);
    if (v <= u) lo += 1;
    return lo;
}

__global__ void __launch_bounds__(WPB * 32, 8)
nerf_kernel(const float* __restrict__ rays,
            const float* __restrict__ sigc,
            const float* __restrict__ rgbc,
            const float* __restrict__ sigf,
            const float* __restrict__ rgbf,
            float* __restrict__ out,
            int N)
{
    __shared__ __align__(16) float smem[WPB][128];   // merged z
    __shared__ __align__(16) float osm[WPB][164];    // 8 q's x 16 partials + fr/wsum/wsF
    const int lane = threadIdx.x & 31;
    const int w    = threadIdx.x >> 5;
    const int ray  = blockIdx.x * WPB + w;

    if (ray < N) {
        float* ZM = smem[w];          // 128 merged z

        float2 nf = *(const float2*)(rays + (size_t)ray * 8 + 6);
        const float nr = nf.x, fr = nf.y;
        const float dzs = (fr - nr) * 0.015625f;     // (far-near)/64
        const float invstep = 1.0f / dzs;

        // ============== coarse pass: lane handles samples 2l, 2l+1 ==============
        const int s0 = lane * 2, s1 = s0 + 1;
        float z0 = nr + (float)s0 * dzs;
        float z1 = nr + (float)s1 * dzs;

        // exp(-d*s) = exp2((-d*log2e)*s); -d*log2e pre-folded (d uniform = dzs)
        const float ndl2  = dzs * -1.442695041f;
        const float ndl2b = (lane == 31) ? -1.442695041e10f : ndl2;  // delta_inf

        float2 sg = *(const float2*)(sigc + (size_t)ray * 64 + s0);
        float e0 = exp2f(ndl2  * fmaxf(sg.x, 0.0f));
        float e1 = exp2f(ndl2b * fmaxf(sg.y, 0.0f));
        float a0 = 1.0f - e0, a1 = 1.0f - e1;
        float f0 = e0 + 1e-10f, f1 = e1 + 1e-10f;

        float fp = f0 * f1;
        float E  = warpExclProd(fp, lane);
        float T0 = E, T1 = E * f0;
        float w0 = a0 * T0, w1 = a1 * T1;

        // telescoped weight sum: sum(a_i T_i) = 1 - prod(f_i) + eps*sum(T_i),
        // eps-term <= 6.4e-9 abs -> drop it. prod(f) = lane31's inclusive scan.
        {
            float Pc = __shfl_sync(FULLMASK, E * fp, 31);
            if (lane == 0) osm[w][161] = 1.0f - Pc;      // wsum
        }

        const float* rp = rgbc + (size_t)ray * 192 + lane * 6;
        float2 ra  = *(const float2*)(rp);
        float2 rb  = *(const float2*)(rp + 2);
        float2 rc2 = *(const float2*)(rp + 4);

        float pR = warpSum1(w0 * ra.x + w1 * rb.y);
        float pG = warpSum1(w0 * ra.y + w1 * rc2.x);
        float pB = warpSum1(w0 * rb.x + w1 * rc2.y);
        float pD = warpSum1(w0 * z0 + w1 * z1);
        if (lane < 16) {
            osm[w][0   + lane] = pR;   // q0 accR
            osm[w][16  + lane] = pG;   // q1 accG
            osm[w][32  + lane] = pB;   // q2 accB
            osm[w][64  + lane] = pD;   // q4 dep
        }
        if (lane == 0) osm[w][160] = fr;

        // ---- cdf over weights[1..62] + 1e-5: registers, 2 entries/lane ----
        float t0c = (s0 >= 1)  ? (w0 + 1e-5f) : 0.0f;
        float t1c = (s1 <= 62) ? (w1 + 1e-5f) : 0.0f;
        float incl = warpInclSum(t0c + t1c, lane);
        float totw = __shfl_sync(FULLMASK, incl, 31);
        float exS  = __shfl_up_sync(FULLMASK, incl, 1);
        if (lane == 0) exS = 0.0f;
        float inv = 1.0f / totw;
        float cdfE = (exS + t0c) * inv;
        float cdfO = (lane == 31) ? 3.0e38f : (incl * inv);

        // ============== fine z: inverse CDF via shuffle search, j = 2l, 2l+1 =========
        float zfine[2];
        int   cfin[2];   // c_j ≈ #{z_coarse <= z_fine_j} (analytic; monotonized below)
        #pragma unroll
        for (int q = 0; q < 2; q++) {
            int j = 2 * lane + q;
            float u = (j == 63) ? 1.0f : (float)j * (1.0f / 63.0f);

            // ind = searchsorted(cdf[0..62], u, 'right')
            int ne = cntLE_f(cdfE, u);                       // in [1,32]
            float oprev = __shfl_sync(FULLMASK, cdfO, ne - 1);
            int t = (oprev <= u) ? 1 : 0;
            int ind = 2 * ne - 1 + t;                        // in [1,63]
            float eprev = __shfl_sync(FULLMASK, cdfE, ne - 1);
            float enext = __shfl_sync(FULLMASK, cdfE, min(ne, 31));

            int below = ind - 1;
            int above = ind < 62 ? ind : 62;
            float cb = t ? oprev : eprev;
            float ca = (t || ind == 63) ? enext : oprev;

            float bb = nr + ((float)below + 0.5f) * dzs;     // bin midpoints
            float ba = nr + ((float)above + 0.5f) * dzs;
            float den = ca - cb;
            if (den < 1e-5f) den = 1.0f;
            float zf = bb + __fdividef(u - cb, den) * (ba - bb);
            zfine[q] = zf;

            // analytic coarse-count; ties resolved by the monotonize pass
            int c = (int)((zf - nr) * invstep) + 1;
            cfin[q] = max(0, min(64, c));
        }

        // ============== monotonize c (running max) — makes the merge a bijection ====
        int c0 = cfin[0], c1 = cfin[1];
        {
            int hi = max(c0, c1);
            int scan = hi;
            #pragma unroll
            for (int d = 1; d < 32; d <<= 1) {
                int o = __shfl_up_sync(FULLMASK, scan, d);
                if (lane >= d) scan = max(scan, o);
            }
            int ex = __shfl_up_sync(FULLMASK, scan, 1);
            if (lane == 0) ex = 0;
            c0 = max(ex, c0);
            c1 = max(c0, c1);
        }
        ZM[2 * lane + c0]     = zfine[0];      // fine merged position = j + c'_j
        ZM[2 * lane + 1 + c1] = zfine[1];

        // ============== coarse merged positions via duality on c' ==============
        #pragma unroll
        for (int q = 0; q < 2; q++) {
            int i = 2 * lane + q;
            int ne = cntLE_i(c0, i);                        // in [0,32]
            int src = ne > 0 ? ne - 1 : 0;
            int cprev = __shfl_sync(FULLMASK, c1, src);
            int cnt = ne > 0 ? (2 * ne - 1 + (cprev <= i ? 1 : 0)) : 0;
            ZM[i + cnt] = (q == 0) ? z0 : z1;
        }
        __syncwarp();

        // ============== fine composite: lane handles samples 4l..4l+3 ==============
        float4 zq = *(const float4*)&ZM[4 * lane];
        float zn  = __shfl_down_sync(FULLMASK, zq.x, 1);   // ZM[4l+4] = lane l+1's zq.x
        float dd0 = zq.y - zq.x;
        float dd1 = zq.z - zq.y;
        float dd2 = zq.w - zq.z;
        float dd3 = (lane == 31) ? 1e10f : (zn - zq.w);

        float4 sg4 = *(const float4*)(sigf + (size_t)ray * 128 + 4 * lane);
        float ee0 = __expf(-dd0 * fmaxf(sg4.x, 0.0f));
        float ee1 = __expf(-dd1 * fmaxf(sg4.y, 0.0f));
        float ee2 = __expf(-dd2 * fmaxf(sg4.z, 0.0f));
        float ee3 = __expf(-dd3 * fmaxf(sg4.w, 0.0f));
        float fa0 = 1.0f - ee0, fa1 = 1.0f - ee1, fa2 = 1.0f - ee2, fa3 = 1.0f - ee3;
        float ff0 = ee0 + 1e-10f, ff1 = ee1 + 1e-10f, ff2 = ee2 + 1e-10f, ff3 = ee3 + 1e-10f;

        float ffp = (ff0 * ff1) * (ff2 * ff3);
        float E2 = warpExclProd(ffp, lane);
        float U0 = E2, U1 = U0 * ff0, U2 = U1 * ff1, U3 = U2 * ff2;
        float v0 = fa0 * U0, v1 = fa1 * U1, v2 = fa2 * U2, v3 = fa3 * U3;

        // telescoped fine weight sum: wsF = 1 - prod(ff)
        {
            float Pf = __shfl_sync(FULLMASK, E2 * ffp, 31);
            if (lane == 0) osm[w][162] = 1.0f - Pf;      // wsF
        }

        const float* rfp = rgbf + (size_t)ray * 384 + 12 * lane;
        float4 q0 = *(const float4*)(rfp);
        float4 q1 = *(const float4*)(rfp + 4);
        float4 q2 = *(const float4*)(rfp + 8);

        float pFR = warpSum1(v0 * q0.x + v1 * q0.w + v2 * q1.z + v3 * q2.y);
        float pFG = warpSum1(v0 * q0.y + v1 * q1.x + v2 * q1.w + v3 * q2.z);
        float pFB = warpSum1(v0 * q0.z + v1 * q1.y + v2 * q2.x + v3 * q2.w);
        float pFD = warpSum1(v0 * zq.x + v1 * zq.y + v2 * zq.z + v3 * zq.w);
        if (lane < 16) {
            osm[w][80  + lane] = pFR;  // q5 fR
            osm[w][96  + lane] = pFG;  // q6 fG
            osm[w][112 + lane] = pFB;  // q7 fB
            osm[w][144 + lane] = pFD;  // q9 depF
        }
    }
    __syncthreads();

    // ============== output phase: finish reductions + coalesced writes ==============
    const int t = threadIdx.x;
    const size_t R0 = (size_t)blockIdx.x * WPB;
    const int nblk = min(WPB, N - (int)R0);
    const size_t NN = (size_t)N;

    #define SUMQ(r, q) ({ const float4* _b = (const float4*)&osm[(r)][16 * (q)]; \
                          float4 _p0 = _b[0], _p1 = _b[1], _p2 = _b[2], _p3 = _b[3]; \
                          (((_p0.x + _p0.y) + (_p0.z + _p0.w)) +                 \
                           ((_p1.x + _p1.y) + (_p1.z + _p1.w))) +                \
                          (((_p2.x + _p2.y) + (_p2.z + _p2.w)) +                 \
                           ((_p3.x + _p3.y) + (_p3.z + _p3.w))); })

    if (t < 24) {                               // coarse rgb
        int r = t / 3, c = t % 3;
        if (r < nblk) out[3 * R0 + t] = SUMQ(r, c) + 1.0f - osm[r][161];
    } else if (t < 32) {                        // coarse alpha (weights_sum)
        int r = t - 24;
        if (r < nblk) out[3 * NN + R0 + r] = osm[r][161];
    } else if (t < 40) {                        // coarse depth
        int r = t - 32;
        if (r < nblk) out[4 * NN + R0 + r] = SUMQ(r, 4) + (1.0f - osm[r][161]) * osm[r][160];
    } else if (t < 64) {                        // fine rgb
        int j = t - 40;
        int r = j / 3, c = j % 3;
        if (r < nblk) out[5 * NN + 3 * R0 + j] = SUMQ(r, 5 + c) + 1.0f - osm[r][162];
    } else if (t < 72) {                        // fine alpha
        int r = t - 64;
        if (r < nblk) out[8 * NN + R0 + r] = osm[r][162];
    } else if (t < 80) {                        // fine depth
        int r = t - 72;
        if (r < nblk) out[9 * NN + R0 + r] = SUMQ(r, 9) + (1.0f - osm[r][162]) * osm[r][160];
    }
    #undef SUMQ
}

extern "C" void kernel_launch(void* const* d_in, const int* in_sizes, int n_in,
                              void* d_out, int out_size) {
    const float* rays = (const float*)d_in[0];
    const float* sc   = (const float*)d_in[1];
    const float* rc   = (const float*)d_in[2];
    const float* sf   = (const float*)d_in[3];
    const float* rf   = (const float*)d_in[4];
    float* out = (float*)d_out;
    int N = in_sizes[0] / 8;
    int blocks = (N + WPB - 1) / WPB;
    nerf_kernel<<<blocks, WPB * 32>>>(rays, sc, rc, sf, rf, out, N);
}